// round 16
// baseline (speedup 1.0000x reference)
#include <cuda_runtime.h>

// out[b,o,d,h,w] = bias[o] + sum_{i=d-2..d+2 in [0,10)} sum_{kh,kw}
//                    x[b,i,h+kh-2,w+kw-2] * W[o,i,i-d+2,kh,kw]
//
// Inputs: x[32,10,128,128] f32, W[10,10,5,5,5] f32, b[10] f32
// Output: [32,10,10,128,128] f32
//
// R14: p=8 pixel strips without register spills. 128-thread CTAs on 32x32
// tiles, __launch_bounds__(128,3) -> 170-reg budget (R13's p=8 at a 128-reg
// cap spilled). Scalar x LDS at pitch 37 + o-contiguous LDS.64 broadcast
// weights (the proven operand path). Double-buffered weight slice -> one
// barrier per job. Persistent 444 CTAs over 5120 tile-major (tile,d) jobs.

#define HW 128
#define NC 10
#define NCTAS 444
#define NJOBS 5120             // 512 tiles (32b x 4ht x 4wt) * 10 d

typedef unsigned long long u64;

#define FMA2(d_, a_, b_, c_) \
    asm("fma.rn.f32x2 %0, %1, %2, %3;" : "=l"(d_) : "l"(a_), "l"(b_), "l"(c_))
#define PACK2(out_, lo_, hi_) \
    asm("mov.b64 %0, {%1, %2};" : "=l"(out_) : "f"(lo_), "f"(hi_))
#define UNPACK2(lo_, hi_, in_) \
    asm("mov.b64 {%0, %1}, %2;" : "=f"(lo_), "=f"(hi_) : "l"(in_))

// Repacked weights: [d][ip][kh][kw][o], zero where i=d+ip-2 out of range.
__device__ float g_Wr[10 * 5 * 5 * 5 * 10];

__global__ void repack_kernel(const float* __restrict__ W) {
    int idx = blockIdx.x * blockDim.x + threadIdx.x;
    if (idx >= 12500) return;
    int o    = idx % 10;
    int rest = idx / 10;
    int kw = rest % 5; rest /= 5;
    int kh = rest % 5; rest /= 5;
    int ip = rest % 5;
    int d  = rest / 5;
    int i = d + ip - 2;
    float v = 0.0f;
    if (i >= 0 && i < 10)
        v = W[o * 1250 + i * 125 + ip * 25 + kh * 5 + kw];
    g_Wr[idx] = v;
}

// SMEM: xs 10ch x 36rows x pitch37 | ws double buffer 2x1250
#define XPITCH 37
#define XROWS  36                          // 32 + 4 halo
#define XS_FLOATS (10 * XROWS * XPITCH)    // 13320
#define WSLICE 1250
#define SMEM_FLOATS (XS_FLOATS + 2 * WSLICE)   // 15820 fl = 63280 B... too big!
// 63280 * 3 = 189840 <= 227KB: OK.

__global__ __launch_bounds__(128, 3) void conv_main(
    const float* __restrict__ x,
    const float* __restrict__ bias,
    float* __restrict__ out)
{
    extern __shared__ float smem[];
    float* xs = smem;
    float* wsbuf = smem + XS_FLOATS;     // byte 53280, 8B aligned; 2 slices

    const int tid = threadIdx.x;
    const int cta = blockIdx.x;

    // contiguous job range: NJOBS = NCTAS*11 + 236
    const int q = NJOBS / NCTAS;
    const int r = NJOBS % NCTAS;
    int job = cta * q + ((cta < r) ? cta : r);
    const int jobEnd = job + q + (cta < r ? 1 : 0);

    const int hh = tid >> 2;             // 0..31
    const int ww = (tid & 3) << 3;       // 0,8,16,24

    // bias pairs in registers
    u64 bp[5];
    #pragma unroll
    for (int o2 = 0; o2 < 5; ++o2) {
        float b0 = __ldg(bias + 2 * o2);
        float b1 = __ldg(bias + 2 * o2 + 1);
        PACK2(bp[o2], b0, b1);
    }

    // ---- prologue: stage first job's weight slice into buf0 ----
    {
        const float* src = g_Wr + (job % 10) * WSLICE;
        for (int k = tid; k < WSLICE; k += 128)
            wsbuf[k] = __ldg(src + k);
    }
    // visibility: first job always takes the tile-change barrier below

    int curTile = -1;
    int buf = 0;
    float* outp = out;

    for (; job < jobEnd; ++job, buf ^= 1) {
        const int d  = job % 10;
        const int tj = job / 10;

        // ---- tile change: reload xs (all warps passed prev end-barrier) ----
        if (tj != curTile) {
            curTile = tj;
            const int b = tj >> 4;
            const int t = tj & 15;
            const int h0 = (t >> 2) << 5;    // 4 htiles of 32 rows
            const int w0 = (t & 3) << 5;     // 4 wtiles of 32 cols
            const float* xb = x + b * (NC * HW * HW);
            outp = out + b * (100 * HW * HW) + (h0 + hh) * HW + (w0 + ww);

            for (int idx = tid; idx < 10 * XROWS * 36; idx += 128) {
                int c   = idx / (XROWS * 36);
                int rem = idx - c * (XROWS * 36);
                int rr_ = rem / 36;
                int col = rem - rr_ * 36;
                int gh = h0 + rr_ - 2;
                int gw = w0 + col - 2;
                float v = 0.0f;
                if ((unsigned)gh < 128u && (unsigned)gw < 128u)
                    v = __ldg(xb + c * (HW * HW) + gh * HW + gw);
                xs[(c * XROWS + rr_) * XPITCH + col] = v;
            }
            __syncthreads();   // xs (and prologue/staged ws) visible
        }

        const float* ws = wsbuf + buf * WSLICE;

        u64 acc[5][8];
        #pragma unroll
        for (int o2 = 0; o2 < 5; ++o2) {
            #pragma unroll
            for (int p = 0; p < 8; ++p) acc[o2][p] = bp[o2];
        }

        const int iLo = (d > 2) ? d - 2 : 0;
        const int iHi = (d < 7) ? d + 2 : 9;

        for (int i = iLo; i <= iHi; ++i) {
            const int ip = i - d + 2;
            const float* wbase = ws + ip * 250;            // 5kh x 5kw x 10o
            const float* xbase = xs + (i * XROWS + hh) * XPITCH + ww;

            #pragma unroll
            for (int kh = 0; kh < 5; ++kh) {
                // scalar x window: 12 values cover kw(0..4)+px(0..7)
                const float* xr = xbase + kh * XPITCH;
                float rv[12];
                #pragma unroll
                for (int tt = 0; tt < 12; ++tt) rv[tt] = xr[tt];
                u64 rr[12];
                #pragma unroll
                for (int tt = 0; tt < 12; ++tt) PACK2(rr[tt], rv[tt], rv[tt]);

                const u64* wk2 = (const u64*)(wbase + kh * 50);   // 8B aligned
                #pragma unroll
                for (int kw = 0; kw < 5; ++kw) {
                    u64 w[5];
                    #pragma unroll
                    for (int o2 = 0; o2 < 5; ++o2) w[o2] = wk2[kw * 5 + o2];
                    #pragma unroll
                    for (int o2 = 0; o2 < 5; ++o2) {
                        #pragma unroll
                        for (int p = 0; p < 8; ++p)
                            FMA2(acc[o2][p], w[o2], rr[kw + p], acc[o2][p]);
                    }
                }
            }
        }

        // ---- store: 8 px per o => two float4 per o ----
        #pragma unroll
        for (int o2 = 0; o2 < 5; ++o2) {
            float lo[8], hi[8];
            #pragma unroll
            for (int p = 0; p < 8; ++p) UNPACK2(lo[p], hi[p], acc[o2][p]);
            float* pa = outp + ((2 * o2) * 10 + d) * (HW * HW);
            float* pb = outp + ((2 * o2 + 1) * 10 + d) * (HW * HW);
            *(float4*)(pa)     = make_float4(lo[0], lo[1], lo[2], lo[3]);
            *(float4*)(pa + 4) = make_float4(lo[4], lo[5], lo[6], lo[7]);
            *(float4*)(pb)     = make_float4(hi[0], hi[1], hi[2], hi[3]);
            *(float4*)(pb + 4) = make_float4(hi[4], hi[5], hi[6], hi[7]);
        }

        // ---- stage NEXT job's weight slice into the other buffer ----
        if (job + 1 < jobEnd) {
            const float* src = g_Wr + ((job + 1) % 10) * WSLICE;
            float* dst = wsbuf + (buf ^ 1) * WSLICE;
            for (int k = tid; k < WSLICE; k += 128)
                dst[k] = __ldg(src + k);
        }
        __syncthreads();   // single per-job barrier: orders compute/store(job)
                           // + staged ws before next iteration's reads/writes
    }
}

extern "C" void kernel_launch(void* const* d_in, const int* in_sizes, int n_in,
                              void* d_out, int out_size) {
    const float* x    = (const float*)d_in[0];
    const float* W    = (const float*)d_in[1];
    const float* bias = (const float*)d_in[2];
    float* out = (float*)d_out;

    repack_kernel<<<49, 256>>>(W);

    const size_t smem_bytes = SMEM_FLOATS * sizeof(float);   // 63280
    cudaFuncSetAttribute(conv_main, cudaFuncAttributeMaxDynamicSharedMemorySize,
                         (int)smem_bytes);

    conv_main<<<NCTAS, 128, smem_bytes>>>(x, bias, out);
}

// round 17
// speedup vs baseline: 1.0758x; 1.0758x over previous
#include <cuda_runtime.h>

// out[b,o,d,h,w] = bias[o] + sum_{i=d-2..d+2 in [0,10)} sum_{kh,kw}
//                    x[b,i,h+kh-2,w+kw-2] * W[o,i,i-d+2,kh,kw]
//
// Inputs: x[32,10,128,128] f32, W[10,10,5,5,5] f32, b[10] f32
// Output: [32,10,10,128,128] f32
//
// R17 = R5 engine (128thr, 16x32 tile, p=4, scalar x LDS at pitch 37) with
// the weight path moved to broadcast __ldg from gmem: per kw one
// LDG.128 pair + LDG.64 yields the five (w[2o],w[2o+1]) u64 operands
// directly (rows padded to 12 floats = 48B, 16B-aligned -> NO packs; this
// fixes R11's float4+PACK mistake). Deletes the per-d weight staging and
// BOTH per-d barriers: warps free-run the whole d loop after one tile sync.

#define NB 32
#define NC 10
#define HW 128

typedef unsigned long long u64;

#define FMA2(d_, a_, b_, c_) \
    asm("fma.rn.f32x2 %0, %1, %2, %3;" : "=l"(d_) : "l"(a_), "l"(b_), "l"(c_))
#define PACK2(out_, lo_, hi_) \
    asm("mov.b64 %0, {%1, %2};" : "=l"(out_) : "f"(lo_), "f"(hi_))
#define UNPACK2(lo_, hi_, in_) \
    asm("mov.b64 {%0, %1}, %2;" : "=f"(lo_), "=f"(hi_) : "l"(in_))

// Repacked weights: [d][ip][kh][kw][12]; j<10 -> W[o=j, i=d+ip-2, ip, kh, kw]
// (zero for invalid i and pad j=10,11). 48B rows, 16B-aligned.
#define WROW 12
__device__ __align__(16) float g_W12[10 * 5 * 5 * 5 * WROW];   // 60000B

__global__ void repack_kernel(const float* __restrict__ W) {
    int idx = blockIdx.x * blockDim.x + threadIdx.x;
    if (idx >= 10 * 5 * 5 * 5 * WROW) return;
    int j    = idx % WROW;
    int rest = idx / WROW;
    int kw = rest % 5; rest /= 5;
    int kh = rest % 5; rest /= 5;
    int ip = rest % 5;
    int d  = rest / 5;
    int i = d + ip - 2;
    float v = 0.0f;
    if (j < 10 && i >= 0 && i < 10)
        v = W[j * 1250 + i * 125 + ip * 25 + kh * 5 + kw];
    g_W12[idx] = v;
}

// SMEM: xs 10ch x 20rows x pitch37 only (29600B)
#define XPITCH 37
#define XS_FLOATS (10 * 20 * XPITCH)        // 7400
#define SMEM_FLOATS XS_FLOATS

__global__ __launch_bounds__(128, 4) void conv_main(
    const float* __restrict__ x,
    const float* __restrict__ bias,
    float* __restrict__ out)
{
    extern __shared__ float smem[];
    float* xs = smem;

    const int b  = blockIdx.x >> 5;
    const int t  = blockIdx.x & 31;
    const int h0 = (t >> 2) << 4;      // 8 htiles of 16 rows
    const int w0 = (t & 3) << 5;       // 4 wtiles of 32 cols
    const int tid = threadIdx.x;

    // ---- load x tile with halo: 10 ch x 20 rows x 36 cols ----
    const float* xb = x + b * (NC * HW * HW);
    for (int idx = tid; idx < 10 * 20 * 36; idx += 128) {
        int c   = idx / 720;
        int rem = idx - c * 720;
        int r   = rem / 36;
        int col = rem - r * 36;
        int gh = h0 + r - 2;
        int gw = w0 + col - 2;
        float v = 0.0f;
        if ((unsigned)gh < 128u && (unsigned)gw < 128u)
            v = __ldg(xb + c * (HW * HW) + gh * HW + gw);
        xs[(c * 20 + r) * XPITCH + col] = v;
    }

    // bias pairs in registers
    u64 bp[5];
    #pragma unroll
    for (int o2 = 0; o2 < 5; ++o2) {
        float b0 = __ldg(bias + 2 * o2);
        float b1 = __ldg(bias + 2 * o2 + 1);
        PACK2(bp[o2], b0, b1);
    }

    __syncthreads();                    // the ONLY block barrier

    const int hh = tid >> 3;            // 0..15
    const int ww = (tid & 7) << 2;      // 0..28
    float* outp = out + b * (100 * HW * HW) + (h0 + hh) * HW + (w0 + ww);

    for (int d = 0; d < 10; ++d) {
        u64 acc[5][4];
        #pragma unroll
        for (int o2 = 0; o2 < 5; ++o2) {
            #pragma unroll
            for (int p = 0; p < 4; ++p) acc[o2][p] = bp[o2];
        }

        const int iLo = (d > 2) ? d - 2 : 0;
        const int iHi = (d < 7) ? d + 2 : 9;

        for (int i = iLo; i <= iHi; ++i) {
            const int ip = i - d + 2;
            const float* wbase = g_W12 + ((d * 5 + ip) * 25) * WROW;
            const float* xbase = xs + (i * 20 + hh) * XPITCH + ww;

            #pragma unroll
            for (int kh = 0; kh < 5; ++kh) {
                // scalar x window: 8 values cover kw(0..4)+px(0..3)
                const float* xr = xbase + kh * XPITCH;
                float rv[8];
                #pragma unroll
                for (int tt = 0; tt < 8; ++tt) rv[tt] = xr[tt];
                u64 rr[8];
                #pragma unroll
                for (int tt = 0; tt < 8; ++tt) PACK2(rr[tt], rv[tt], rv[tt]);

                const float* wk = wbase + kh * (5 * WROW);
                #pragma unroll
                for (int kw = 0; kw < 5; ++kw) {
                    // 48B-aligned row: LDG.128 x2 + LDG.64, operands pre-paired
                    const float* wr = wk + kw * WROW;
                    ulonglong2 q0 = __ldg((const ulonglong2*)wr);
                    ulonglong2 q1 = __ldg((const ulonglong2*)(wr + 4));
                    u64 w4        = __ldg((const u64*)(wr + 8));
                    u64 w[5] = {q0.x, q0.y, q1.x, q1.y, w4};
                    #pragma unroll
                    for (int o2 = 0; o2 < 5; ++o2) {
                        #pragma unroll
                        for (int p = 0; p < 4; ++p)
                            FMA2(acc[o2][p], w[o2], rr[kw + p], acc[o2][p]);
                    }
                }
            }
        }

        // ---- store: two float4 per o-pair ----
        #pragma unroll
        for (int o2 = 0; o2 < 5; ++o2) {
            float lo0, hi0, lo1, hi1, lo2, hi2, lo3, hi3;
            UNPACK2(lo0, hi0, acc[o2][0]);
            UNPACK2(lo1, hi1, acc[o2][1]);
            UNPACK2(lo2, hi2, acc[o2][2]);
            UNPACK2(lo3, hi3, acc[o2][3]);
            float4 sa = make_float4(lo0, lo1, lo2, lo3);
            float4 sb = make_float4(hi0, hi1, hi2, hi3);
            *(float4*)(outp + ((2 * o2) * 10 + d) * (HW * HW))     = sa;
            *(float4*)(outp + ((2 * o2 + 1) * 10 + d) * (HW * HW)) = sb;
        }
    }
}

extern "C" void kernel_launch(void* const* d_in, const int* in_sizes, int n_in,
                              void* d_out, int out_size) {
    const float* x    = (const float*)d_in[0];
    const float* W    = (const float*)d_in[1];
    const float* bias = (const float*)d_in[2];
    float* out = (float*)d_out;

    repack_kernel<<<59, 256>>>(W);

    const size_t smem_bytes = SMEM_FLOATS * sizeof(float);   // 29600
    conv_main<<<NB * 32, 128, smem_bytes>>>(x, bias, out);
}